// round 7
// baseline (speedup 1.0000x reference)
#include <cuda_runtime.h>
#include <math.h>

static constexpr int D      = 512;    // feature dim (float32)
static constexpr int BLOCK  = 256;    // 8 warps per block
static constexpr int GRID   = 1184;   // 148 SMs * 8 resident blocks (persistent)

__device__ float        g_partials[GRID];
__device__ unsigned int g_done;       // zero at module load; self-resets per launch

__device__ __forceinline__ float ldcg(const float* p) {
    float v;
    asm volatile("ld.global.cg.f32 %0, [%1];" : "=f"(v) : "l"(p));
    return v;
}

// Persistent kernel: one warp per edge per grid-stride step. Gather two rows,
// dot, BCE-with-logits term. Block partials reduced deterministically; the
// last block to finish reduces the 1184 partials and writes the mean.
__global__ void __launch_bounds__(BLOCK) edge_loss_fused_kernel(
    const float* __restrict__ feat,
    const int*   __restrict__ pos_src,
    const int*   __restrict__ pos_dst,
    const int*   __restrict__ neg_src,
    const int*   __restrict__ neg_dst,
    int e_pos, int e_total, float inv_total,
    float* __restrict__ out)
{
    const int lane = threadIdx.x & 31;
    const int wid  = threadIdx.x >> 5;
    const int warp_global = (blockIdx.x * BLOCK + threadIdx.x) >> 5;
    const int total_warps = GRID * (BLOCK / 32);

    float wterm = 0.0f;

    for (int e = warp_global; e < e_total; e += total_warps) {
        int s, d;
        const bool is_pos = (e < e_pos);
        if (is_pos) {
            s = pos_src[e];
            d = pos_dst[e];
        } else {
            s = neg_src[e - e_pos];
            d = neg_dst[e - e_pos];
        }

        const float4* __restrict__ u =
            reinterpret_cast<const float4*>(feat + (size_t)s * D);
        const float4* __restrict__ v =
            reinterpret_cast<const float4*>(feat + (size_t)d * D);

        // 512 floats = 128 float4 per row; lane takes 4 at stride 32.
        // All 8 vector loads issued up front for MLP.
        float4 a0 = u[lane +  0];
        float4 a1 = u[lane + 32];
        float4 a2 = u[lane + 64];
        float4 a3 = u[lane + 96];
        float4 b0 = v[lane +  0];
        float4 b1 = v[lane + 32];
        float4 b2 = v[lane + 64];
        float4 b3 = v[lane + 96];

        float acc = 0.0f;
        acc = fmaf(a0.x, b0.x, acc); acc = fmaf(a0.y, b0.y, acc);
        acc = fmaf(a0.z, b0.z, acc); acc = fmaf(a0.w, b0.w, acc);
        acc = fmaf(a1.x, b1.x, acc); acc = fmaf(a1.y, b1.y, acc);
        acc = fmaf(a1.z, b1.z, acc); acc = fmaf(a1.w, b1.w, acc);
        acc = fmaf(a2.x, b2.x, acc); acc = fmaf(a2.y, b2.y, acc);
        acc = fmaf(a2.z, b2.z, acc); acc = fmaf(a2.w, b2.w, acc);
        acc = fmaf(a3.x, b3.x, acc); acc = fmaf(a3.y, b3.y, acc);
        acc = fmaf(a3.z, b3.z, acc); acc = fmaf(a3.w, b3.w, acc);

        // Warp reduce (deterministic tree).
        #pragma unroll
        for (int off = 16; off > 0; off >>= 1)
            acc += __shfl_xor_sync(0xffffffffu, acc, off);

        const float lab = is_pos ? 1.0f : 0.0f;
        wterm += fmaxf(acc, 0.0f) - acc * lab + log1pf(expf(-fabsf(acc)));
    }

    // Block reduce in fixed order.
    __shared__ float smem[BLOCK / 32];
    __shared__ bool  is_last;
    if (lane == 0) smem[wid] = wterm;
    __syncthreads();
    if (threadIdx.x == 0) {
        float sum = 0.0f;
        #pragma unroll
        for (int i = 0; i < BLOCK / 32; i++) sum += smem[i];
        g_partials[blockIdx.x] = sum;
        __threadfence();
        unsigned int old = atomicAdd(&g_done, 1u);
        is_last = (old == (unsigned int)(gridDim.x - 1));
    }
    __syncthreads();

    // Last block reduces all partials (fixed tree order -> deterministic).
    if (is_last) {
        __shared__ float red[BLOCK];
        float a = 0.0f;
        for (int i = threadIdx.x; i < GRID; i += BLOCK)
            a += ldcg(&g_partials[i]);           // L1-bypass: coherent read
        red[threadIdx.x] = a;
        __syncthreads();
        #pragma unroll
        for (int s = BLOCK / 2; s > 0; s >>= 1) {
            if (threadIdx.x < s) red[threadIdx.x] += red[threadIdx.x + s];
            __syncthreads();
        }
        if (threadIdx.x == 0) {
            *out   = red[0] * inv_total;
            g_done = 0;                          // reset for next graph replay
        }
    }
}

extern "C" void kernel_launch(void* const* d_in, const int* in_sizes, int n_in,
                              void* d_out, int out_size)
{
    const float* feat    = (const float*)d_in[0];
    const int*   pos_src = (const int*)d_in[1];
    const int*   pos_dst = (const int*)d_in[2];
    const int*   neg_src = (const int*)d_in[3];
    const int*   neg_dst = (const int*)d_in[4];
    float* out = (float*)d_out;

    const int e_pos   = in_sizes[1];
    const int e_neg   = in_sizes[3];
    const int e_total = e_pos + e_neg;

    edge_loss_fused_kernel<<<GRID, BLOCK>>>(feat, pos_src, pos_dst,
                                            neg_src, neg_dst,
                                            e_pos, e_total,
                                            1.0f / (float)e_total, out);
}